// round 7
// baseline (speedup 1.0000x reference)
#include <cuda_runtime.h>
#include <math.h>

#define EMAX 4096
#define CAP  (EMAX*(EMAX-1)/2)
#define NB   35                    // angle buckets; width pi/35 > THR with slack
#define BINSCALE 11.140846f        // 35 / pi
#define CAPC 1024
#define NBLK 128
#define NTHR 512

// ---- device scratch (no allocations allowed) ----
__device__ float4  g_i4[EMAX];      // (ang, nx, ny, c) by ORIGINAL edge index
__device__ float2  g_mid[EMAX];     // midpoint by original index
__device__ int     g_bin[EMAX];
__device__ unsigned g_bcnt[NB], g_bcur[NB], g_boff[NB];
__device__ float4  g_q4[EMAX];      // bucket-order: (ang, mx, my, bitcast(orig idx))
__device__ unsigned g_count;
__device__ float   g_buf[CAP];
__device__ unsigned g_hc[256];      // float bits >> 24
__device__ unsigned g_hf[65536];    // float bits >> 16
__device__ unsigned g_h3[3*256];    // (bits >> 8) & 255, per rank, within picked 16-bit prefix
__device__ unsigned g_p16[3], g_rB[3];
__device__ unsigned g_p24[3], g_rC[3];
__device__ float    g_cand[3*CAPC];
__device__ unsigned g_candn[3];
__device__ unsigned g_done;
__device__ double   g_sum;

#define PI_F  3.14159274101257324f
#define THR_F 0.08726646259971647f

// 256-entry inclusive scan using first 256 threads (all threads hit barriers).
__device__ __forceinline__ unsigned scan256(unsigned* sh, unsigned h)
{
    int t = threadIdx.x;
    if (t < 256) sh[t] = h;
    __syncthreads();
    #pragma unroll
    for (int off = 1; off < 256; off <<= 1) {
        unsigned v = 0;
        if (t < 256) { v = sh[t]; if (t >= off) v += sh[t - off]; }
        __syncthreads();
        if (t < 256) sh[t] = v;
        __syncthreads();
    }
    return (t < 256) ? sh[t] : 0u;
}

// ---------------------------------------------------------------------------
// K1: zero scratch + per-edge geometry + angle-bucket counts.  <<<128,512>>>
// ---------------------------------------------------------------------------
__global__ void k_setup(const float* __restrict__ pos, const int* __restrict__ eidx, int E)
{
    int gtid = blockIdx.x * blockDim.x + threadIdx.x;   // 65536 threads
    g_hf[gtid] = 0u;
    if (gtid < 256)  g_hc[gtid] = 0u;
    if (gtid < 768)  g_h3[gtid] = 0u;
    if (gtid < NB)   { g_bcnt[gtid] = 0u; g_bcur[gtid] = 0u; }
    if (gtid < 3)    g_candn[gtid] = 0u;
    if (gtid == 0)   { g_count = 0u; g_sum = 0.0; g_done = 0u; }

    if (gtid < E) {
        int e = gtid;
        int s = eidx[e];
        int d = eidx[E + e];
        float sx = pos[2*s], sy = pos[2*s+1];
        float dx = pos[2*d], dy = pos[2*d+1];
        float vx = dx - sx, vy = dy - sy;
        float len = fmaxf(sqrtf(vx*vx + vy*vy), 1e-8f);
        float ux = vx / len, uy = vy / len;
        float a = atan2f(uy, ux);
        a = fmodf(a, PI_F);
        if (a < 0.f) a += PI_F;
        float nx = -uy, ny = ux;
        g_i4[e]  = make_float4(a, nx, ny, sx*nx + sy*ny);
        g_mid[e] = make_float2((sx + dx) * 0.5f, (sy + dy) * 0.5f);
        int b = (int)(a * BINSCALE);
        if (b >= NB) b = NB - 1;
        if (b < 0)   b = 0;
        g_bin[e] = b;
        atomicAdd(&g_bcnt[b], 1u);
    }
}

// ---------------------------------------------------------------------------
// K2: scatter edges into bucket-contiguous float4 array.  <<<8,512>>>
// ---------------------------------------------------------------------------
__global__ void k_fill(int E)
{
    int e = blockIdx.x * blockDim.x + threadIdx.x;
    if (e >= E) return;
    if (e < NB) {                       // write bucket start offsets (one writer each)
        unsigned ob = 0;
        for (int k = 0; k < e; k++) ob += g_bcnt[k];
        g_boff[e] = ob;
    }
    int b = g_bin[e];
    unsigned off = 0;
    #pragma unroll
    for (int k = 0; k < NB; k++) off += (k < b) ? g_bcnt[k] : 0u;
    unsigned slot = off + atomicAdd(&g_bcur[b], 1u);
    float4 i4 = g_i4[e];
    float2 m  = g_mid[e];
    g_q4[slot] = make_float4(i4.x, m.x, m.y, __int_as_float(e));
}

// ---------------------------------------------------------------------------
// K3: pair sweep via adjacent buckets. Exact reference predicate per pair;
// emit distances (warp-aggregated) + level-0/1 histograms.  <<<128,512>>>
// ---------------------------------------------------------------------------
__global__ void k_pairs(int E)
{
    const unsigned FULL = 0xFFFFFFFFu;
    int gtid = blockIdx.x * blockDim.x + threadIdx.x;
    int gw   = gtid >> 5;
    int lane = gtid & 31;
    int nw   = (gridDim.x * blockDim.x) >> 5;

    for (int i = gw; i < E; i += nw) {
        float4 f = g_i4[i];
        float ai = f.x, nxi = f.y, nyi = f.z, ci = f.w;
        int bi = g_bin[i];
        #pragma unroll
        for (int db = -1; db <= 1; db++) {
            int b = bi + db;
            if (b < 0)    b += NB;
            if (b >= NB)  b -= NB;
            unsigned st = g_boff[b];
            unsigned en = st + g_bcnt[b];
            for (unsigned basek = st; basek < en; basek += 32) {
                unsigned k = basek + lane;
                bool in = false;
                float dist = 0.f;
                if (k < en) {
                    float4 q = g_q4[k];
                    int j = __float_as_int(q.w);
                    if (j > i) {
                        float da   = fabsf(ai - q.x);
                        float circ = fminf(da, PI_F - da);
                        if (circ <= THR_F) {      // exact reference mask
                            in = true;
                            // i < j: line of edge i, midpoint of edge j (reference)
                            dist = fabsf(fmaf(nxi, q.y, fmaf(nyi, q.z, -ci)));
                        }
                    }
                }
                unsigned ball = __ballot_sync(FULL, in);
                if (ball) {
                    int leader = __ffs(ball) - 1;
                    unsigned bb = 0;
                    if (lane == leader) bb = atomicAdd(&g_count, (unsigned)__popc(ball));
                    bb = __shfl_sync(FULL, bb, leader);
                    if (in) {
                        g_buf[bb + __popc(ball & ((1u << lane) - 1u))] = dist;
                        unsigned bits = __float_as_uint(dist);
                        atomicAdd(&g_hf[bits >> 16], 1u);
                        atomicAdd(&g_hc[bits >> 24], 1u);
                    }
                }
            }
        }
    }
}

// ---------------------------------------------------------------------------
// K4: redundant pick of 16-bit prefix (coarse+fine scans, every block) +
// one pass over g_buf building level-2 (bits>>8 & 255) histograms. <<<128,512>>>
// ---------------------------------------------------------------------------
__global__ void k_h3()
{
    __shared__ unsigned ssc[256];
    __shared__ unsigned s_cb[3], s_rA[3], s_p16[3], s_rB[3];
    int t = threadIdx.x;
    unsigned n = g_count;

    int r0 = (int)(n/4) - 1; if (r0 < 0) r0 = 0;
    int r1 = (int)(n/2);
    int r2 = (int)((3ull*n)/4); if (r2 > (int)n - 1) r2 = (int)n - 1;
    if (r2 < 0) r2 = 0;
    unsigned rr[3] = {(unsigned)r0, (unsigned)r1, (unsigned)r2};

    // level 0: coarse 256
    unsigned h   = (t < 256) ? g_hc[t] : 0u;
    unsigned inc = scan256(ssc, h);
    unsigned exc = inc - h;
    if (t < 256) {
        #pragma unroll
        for (int s = 0; s < 3; s++)
            if (exc <= rr[s] && rr[s] < inc) { s_cb[s] = (unsigned)t; s_rA[s] = rr[s] - exc; }
    }
    __syncthreads();

    // level 1: fine 256 within coarse bin, per rank
    for (int s = 0; s < 3; s++) {
        unsigned cb  = s_cb[s];
        unsigned h2  = (t < 256) ? g_hf[(cb << 8) + t] : 0u;
        unsigned in2 = scan256(ssc, h2);
        unsigned ex2 = in2 - h2;
        unsigned rA  = s_rA[s];
        if (t < 256 && ex2 <= rA && rA < in2) { s_p16[s] = (cb << 8) | (unsigned)t; s_rB[s] = rA - ex2; }
        __syncthreads();
    }
    if (t < 3) { g_p16[t] = s_p16[t]; g_rB[t] = s_rB[t]; }  // duplicate-identical across blocks

    unsigned p0 = s_p16[0], p1 = s_p16[1], p2 = s_p16[2];
    int stride = gridDim.x * blockDim.x;
    for (unsigned idx = blockIdx.x * blockDim.x + t; idx < n; idx += stride) {
        unsigned bits = __float_as_uint(g_buf[idx]);
        unsigned f16 = bits >> 16, b8 = (bits >> 8) & 255u;
        if (f16 == p0) atomicAdd(&g_h3[b8],       1u);
        if (f16 == p1) atomicAdd(&g_h3[256 + b8], 1u);
        if (f16 == p2) atomicAdd(&g_h3[512 + b8], 1u);
    }
}

// ---------------------------------------------------------------------------
// K5: redundant pick of 24-bit prefix + collect exact candidates. <<<128,512>>>
// ---------------------------------------------------------------------------
__global__ void k_collect()
{
    __shared__ unsigned ssc[256];
    __shared__ unsigned s_p24[3], s_rC[3];
    int t = threadIdx.x;
    unsigned n = g_count;

    for (int s = 0; s < 3; s++) {
        unsigned p16 = g_p16[s], rB = g_rB[s];
        unsigned h   = (t < 256) ? g_h3[s * 256 + t] : 0u;
        unsigned inc = scan256(ssc, h);
        unsigned exc = inc - h;
        if (t < 256 && exc <= rB && rB < inc) { s_p24[s] = (p16 << 8) | (unsigned)t; s_rC[s] = rB - exc; }
        __syncthreads();
    }
    if (t < 3) { g_p24[t] = s_p24[t]; g_rC[t] = s_rC[t]; }

    unsigned p0 = s_p24[0], p1 = s_p24[1], p2 = s_p24[2];
    int stride = gridDim.x * blockDim.x;
    for (unsigned idx = blockIdx.x * blockDim.x + t; idx < n; idx += stride) {
        float v = g_buf[idx];
        unsigned q = __float_as_uint(v) >> 8;
        if (q == p0) { unsigned p = atomicAdd(&g_candn[0], 1u); if (p < CAPC) g_cand[p]           = v; }
        if (q == p1) { unsigned p = atomicAdd(&g_candn[1], 1u); if (p < CAPC) g_cand[CAPC   + p]  = v; }
        if (q == p2) { unsigned p = atomicAdd(&g_candn[2], 1u); if (p < CAPC) g_cand[2*CAPC + p]  = v; }
    }
}

// ---------------------------------------------------------------------------
// K6: redundant exact rank-select on tiny candidate sets + hinge loss. <<<128,512>>>
// ---------------------------------------------------------------------------
__global__ void k_loss(float* __restrict__ out)
{
    __shared__ float sq[3];
    int t = threadIdx.x;
    unsigned n = g_count;

    for (int s = 0; s < 3; s++) {
        unsigned c  = g_candn[s]; if (c > CAPC) c = CAPC;
        unsigned rC = g_rC[s];
        const float* cd = &g_cand[s * CAPC];
        for (unsigned i = t; i < c; i += blockDim.x) {
            float v = cd[i];
            unsigned le = 0, eq = 0;
            for (unsigned k = 0; k < c; k++) { float w = cd[k]; le += (w < v); eq += (w == v); }
            if (le <= rC && rC < le + eq) sq[s] = v;   // unique value; dup writes identical
        }
    }
    __syncthreads();

    float q1 = sq[0], mu = sq[1], q3 = sq[2];
    float margin = fmaxf(q3 - q1, 1e-6f) * 0.75f;      // iqr * 0.5 * 1.5

    double local = 0.0;
    int stride = gridDim.x * blockDim.x;
    for (unsigned idx = blockIdx.x * blockDim.x + t; idx < n; idx += stride) {
        float d = g_buf[idx];
        float v = fabsf(d - mu) - margin;
        if (v > 0.f) local += (double)v;
    }
    for (int o = 16; o; o >>= 1) local += __shfl_down_sync(0xFFFFFFFFu, local, o);
    __shared__ double shs[NTHR/32];
    if ((t & 31) == 0) shs[t >> 5] = local;
    __syncthreads();
    if (t < 32) {
        double v = (t < NTHR/32) ? shs[t] : 0.0;
        for (int o = 16; o; o >>= 1) v += __shfl_down_sync(0xFFFFFFFFu, v, o);
        if (t == 0 && v != 0.0) atomicAdd(&g_sum, v);
    }

    __shared__ bool last;
    if (t == 0) {
        __threadfence();
        last = (atomicAdd(&g_done, 1u) == gridDim.x - 1);
    }
    __syncthreads();
    if (last && t == 0) {
        __threadfence();
        double denom = (double)(n > 0u ? n : 1u);
        out[0] = (float)(*(volatile double*)&g_sum / denom);
    }
}

// ---------------------------------------------------------------------------
extern "C" void kernel_launch(void* const* d_in, const int* in_sizes, int n_in,
                              void* d_out, int out_size)
{
    const float* pos  = (const float*)d_in[0];   // node_positions (B*N, 2)
    // d_in[1] = adjacency: unused
    const int*   eidx = (const int*)d_in[2];     // edge_index (2, E)
    float* out = (float*)d_out;

    int E = in_sizes[2] / 2;
    if (E > EMAX) E = EMAX;

    k_setup<<<NBLK, NTHR>>>(pos, eidx, E);
    k_fill<<<8, 512>>>(E);
    k_pairs<<<NBLK, NTHR>>>(E);
    k_h3<<<NBLK, NTHR>>>();
    k_collect<<<NBLK, NTHR>>>();
    k_loss<<<NBLK, NTHR>>>(out);
}

// round 8
// speedup vs baseline: 3.0652x; 3.0652x over previous
#include <cuda_runtime.h>
#include <math.h>

#define EMAX 4096
#define NB2  256
#define W    8
#define PI_F   3.14159274101257324f
#define THR_F  0.08726646259971647f
#define BSCALE 81.48733086305042f     /* 256/pi */

// ---- device scratch (no allocations allowed) ----
__device__ float4   g_i4[EMAX];        // (ang, nx, ny, c) by original edge idx
__device__ float2   g_mid[EMAX];
__device__ int      g_bine[EMAX];
__device__ unsigned g_bcnt[NB2], g_bcur[NB2];
__device__ unsigned g_boff[NB2 + 1];
__device__ float4   g_q4[EMAX];        // bucket-order: (ang, mx, my, bitcast(orig idx))
__device__ unsigned g_hA[2048];        // float bits [21..31]
__device__ unsigned g_hB[3 * 2048];    // bits [10..20] per rank (filtered by A prefix)
__device__ unsigned g_hC[3 * 1024];    // bits [0..9]  per rank (filtered by AB prefix)
__device__ unsigned g_n;
__device__ unsigned g_pA[3], g_rA[3];
__device__ unsigned g_pB[3], g_rB[3];
__device__ unsigned g_done;
__device__ double   g_sum;

// ---------------------------------------------------------------------------
// Shared pair-enumeration. Window of 17 buckets (mod 256) around the scanning
// edge's bucket = 1 or 2 contiguous entry ranges. Exact reference predicate
// per candidate; dist uses the smaller-original-index edge's line (u < v).
// MODE 0: shared-mem histA   MODE 1: global histB (A-prefix filtered)
// MODE 2: global histC (AB-prefix filtered)   MODE 3: hinge accumulate
// ---------------------------------------------------------------------------
template<int MODE>
__device__ __forceinline__ void enumerate(int E, const unsigned* sboff,
                                          const unsigned* pf, unsigned* shh,
                                          float mu, float margin, double& acc)
{
    int gw   = (blockIdx.x * blockDim.x + threadIdx.x) >> 5;
    int lane = threadIdx.x & 31;
    int nw   = (gridDim.x * blockDim.x) >> 5;

    for (int u = gw; u < E; u += nw) {
        float4 f = g_i4[u];
        float au = f.x, nxu = f.y, nyu = f.z, cu = f.w;
        int b  = g_bine[u];
        int lo = b - W, hi = b + W;
        unsigned r0s, r0e, r1s = 0u, r1e = 0u;
        if (lo < 0)         { r0s = sboff[lo + NB2]; r0e = sboff[NB2]; r1s = sboff[0]; r1e = sboff[hi + 1]; }
        else if (hi >= NB2) { r0s = sboff[lo];       r0e = sboff[NB2]; r1s = sboff[0]; r1e = sboff[hi - NB2 + 1]; }
        else                { r0s = sboff[lo];       r0e = sboff[hi + 1]; }

        #pragma unroll
        for (int pass = 0; pass < 2; pass++) {
            unsigned ks = pass ? r1s : r0s;
            unsigned ke = pass ? r1e : r0e;
            for (unsigned k = ks + lane; k < ke; k += 32) {
                float4 q = g_q4[k];
                int v = __float_as_int(q.w);
                if (v <= u) continue;
                float da   = fabsf(au - q.x);
                float circ = fminf(da, PI_F - da);
                if (circ > THR_F) continue;                 // exact reference mask
                float dist = fabsf(fmaf(nxu, q.y, fmaf(nyu, q.z, -cu)));
                unsigned bits = __float_as_uint(dist);
                if (MODE == 0) atomicAdd(&shh[bits >> 21], 1u);
                if (MODE == 1) {
                    unsigned a11 = bits >> 21, m11 = (bits >> 10) & 2047u;
                    if (a11 == pf[0]) atomicAdd(&g_hB[m11],        1u);
                    if (a11 == pf[1]) atomicAdd(&g_hB[2048 + m11], 1u);
                    if (a11 == pf[2]) atomicAdd(&g_hB[4096 + m11], 1u);
                }
                if (MODE == 2) {
                    unsigned ab22 = bits >> 10, l10 = bits & 1023u;
                    if (ab22 == pf[0]) atomicAdd(&g_hC[l10],        1u);
                    if (ab22 == pf[1]) atomicAdd(&g_hC[1024 + l10], 1u);
                    if (ab22 == pf[2]) atomicAdd(&g_hC[2048 + l10], 1u);
                }
                if (MODE == 3) {
                    float h = fabsf(dist - mu) - margin;
                    if (h > 0.f) acc += (double)h;
                }
            }
        }
    }
}

// ---------------------------------------------------------------------------
// K1: zero scratch + per-edge geometry + bucket counts.  <<<32,256>>>
// ---------------------------------------------------------------------------
__global__ void k_setup(const float* __restrict__ pos, const int* __restrict__ eidx, int E)
{
    int gtid = blockIdx.x * blockDim.x + threadIdx.x;     // 8192 threads
    int nt   = gridDim.x * blockDim.x;
    for (int k = gtid; k < 2048;   k += nt) g_hA[k] = 0u;
    for (int k = gtid; k < 3*2048; k += nt) g_hB[k] = 0u;
    for (int k = gtid; k < 3*1024; k += nt) g_hC[k] = 0u;
    if (gtid < NB2) { g_bcnt[gtid] = 0u; g_bcur[gtid] = 0u; }
    if (gtid == 0)  { g_sum = 0.0; g_done = 0u; g_n = 0u; }

    if (gtid < E) {
        int e = gtid;
        int s = eidx[e];
        int d = eidx[E + e];
        float sx = pos[2*s], sy = pos[2*s+1];
        float dx = pos[2*d], dy = pos[2*d+1];
        float vx = dx - sx, vy = dy - sy;
        float len = fmaxf(sqrtf(vx*vx + vy*vy), 1e-8f);
        float ux = vx / len, uy = vy / len;
        float a = atan2f(uy, ux);
        a = fmodf(a, PI_F);
        if (a < 0.f) a += PI_F;
        float nx = -uy, ny = ux;
        g_i4[e]  = make_float4(a, nx, ny, sx*nx + sy*ny);
        g_mid[e] = make_float2((sx + dx) * 0.5f, (sy + dy) * 0.5f);
        int b = (int)(a * BSCALE);
        if (b >= NB2) b = NB2 - 1;
        if (b < 0)    b = 0;
        g_bine[e] = b;
        atomicAdd(&g_bcnt[b], 1u);
    }
}

// ---------------------------------------------------------------------------
// K2: redundant per-block offset scan + bucket scatter.  <<<16,256>>>
// ---------------------------------------------------------------------------
__global__ void k_fill(int E)
{
    __shared__ unsigned sb[NB2 + 1];
    __shared__ unsigned ssc[NB2];
    int t = threadIdx.x;

    unsigned c = g_bcnt[t];
    ssc[t] = c;
    __syncthreads();
    #pragma unroll
    for (int off = 1; off < NB2; off <<= 1) {
        unsigned v = ssc[t];
        unsigned a = (t >= off) ? ssc[t - off] : 0u;
        __syncthreads();
        ssc[t] = v + a;
        __syncthreads();
    }
    unsigned exc = ssc[t] - c;
    sb[t] = exc;
    if (t == NB2 - 1) sb[NB2] = ssc[NB2 - 1];
    g_boff[t] = exc;                                   // identical across blocks
    if (t == NB2 - 1) g_boff[NB2] = ssc[NB2 - 1];
    __syncthreads();

    int e = blockIdx.x * blockDim.x + t;
    if (e < E) {
        int b = g_bine[e];
        unsigned slot = sb[b] + atomicAdd(&g_bcur[b], 1u);
        float4 f = g_i4[e];
        float2 m = g_mid[e];
        g_q4[slot] = make_float4(f.x, m.x, m.y, __int_as_float(e));
    }
}

// ---------------------------------------------------------------------------
// K3: enumeration pass A — shared-mem 2048-bin histogram + flush. <<<128,256>>>
// ---------------------------------------------------------------------------
__global__ void k_histA(int E)
{
    __shared__ unsigned sb[NB2 + 1];
    __shared__ unsigned sh[2048];
    int t = threadIdx.x;
    for (int k = t; k <= NB2; k += 256) sb[k] = g_boff[k];
    for (int k = t; k < 2048; k += 256) sh[k] = 0u;
    __syncthreads();

    double dummy = 0.0;
    enumerate<0>(E, sb, 0, sh, 0.f, 0.f, dummy);
    __syncthreads();
    for (int k = t; k < 2048; k += 256) {
        unsigned v = sh[k];
        if (v) atomicAdd(&g_hA[k], v);
    }
}

// ---------------------------------------------------------------------------
// K4: redundant pickA (2048-bin scan per block) + enumeration pass B. <<<128,256>>>
// ---------------------------------------------------------------------------
__global__ void k_pickA_histB(int E)
{
    __shared__ unsigned sb[NB2 + 1];
    __shared__ unsigned ssc[256];
    __shared__ unsigned sp[3];
    int t = threadIdx.x;
    for (int k = t; k <= NB2; k += 256) sb[k] = g_boff[k];
    if (t < 3) sp[t] = 0xFFFFFFFFu;

    unsigned loc[8], s = 0;
    #pragma unroll
    for (int k = 0; k < 8; k++) { loc[k] = g_hA[t*8 + k]; s += loc[k]; }
    ssc[t] = s;
    __syncthreads();
    #pragma unroll
    for (int off = 1; off < 256; off <<= 1) {
        unsigned v = ssc[t];
        unsigned a = (t >= off) ? ssc[t - off] : 0u;
        __syncthreads();
        ssc[t] = v + a;
        __syncthreads();
    }
    unsigned inc = ssc[t], exc = inc - s;
    unsigned n = ssc[255];
    if (t == 0) g_n = n;                               // identical across blocks

    if (n) {
        unsigned r[3];
        r[0] = (n/4 > 0u) ? (n/4 - 1u) : 0u;
        r[1] = n/2;
        unsigned q3i = (unsigned)((3ull * n) / 4ull);
        if (q3i > n - 1u) q3i = n - 1u;
        r[2] = q3i;
        #pragma unroll
        for (int st = 0; st < 3; st++) {
            if (s && exc <= r[st] && r[st] < inc) {
                unsigned cum = exc;
                #pragma unroll
                for (int k = 0; k < 8; k++) {
                    if (cum + loc[k] > r[st]) {
                        sp[st] = (unsigned)(t*8 + k);
                        g_pA[st] = (unsigned)(t*8 + k);
                        g_rA[st] = r[st] - cum;
                        break;
                    }
                    cum += loc[k];
                }
            }
        }
    }
    __syncthreads();
    if (!n) return;
    unsigned pf[3] = {sp[0], sp[1], sp[2]};
    double dummy = 0.0;
    enumerate<1>(E, sb, pf, 0, 0.f, 0.f, dummy);
}

// ---------------------------------------------------------------------------
// K5: redundant pickB (3 × 2048-bin scans) + enumeration pass C. <<<128,256>>>
// ---------------------------------------------------------------------------
__global__ void k_pickB_histC(int E)
{
    __shared__ unsigned sb[NB2 + 1];
    __shared__ unsigned ssc[256];
    __shared__ unsigned spf[3];
    int t = threadIdx.x;
    for (int k = t; k <= NB2; k += 256) sb[k] = g_boff[k];
    if (t < 3) spf[t] = 0xFFFFFFFFu;
    unsigned n = g_n;
    if (!n) return;

    for (int st = 0; st < 3; st++) {
        unsigned rA = g_rA[st];
        unsigned pA = g_pA[st];
        unsigned loc[8], s = 0;
        #pragma unroll
        for (int k = 0; k < 8; k++) { loc[k] = g_hB[st*2048 + t*8 + k]; s += loc[k]; }
        ssc[t] = s;
        __syncthreads();
        #pragma unroll
        for (int off = 1; off < 256; off <<= 1) {
            unsigned v = ssc[t];
            unsigned a = (t >= off) ? ssc[t - off] : 0u;
            __syncthreads();
            ssc[t] = v + a;
            __syncthreads();
        }
        unsigned inc = ssc[t], exc = inc - s;
        if (s && exc <= rA && rA < inc) {
            unsigned cum = exc;
            #pragma unroll
            for (int k = 0; k < 8; k++) {
                if (cum + loc[k] > rA) {
                    unsigned pb = (unsigned)(t*8 + k);
                    g_pB[st] = pb;
                    g_rB[st] = rA - cum;
                    spf[st]  = (pA << 11) | pb;
                    break;
                }
                cum += loc[k];
            }
        }
        __syncthreads();
    }
    unsigned pf[3] = {spf[0], spf[1], spf[2]};
    double dummy = 0.0;
    enumerate<2>(E, sb, pf, 0, 0.f, 0.f, dummy);
}

// ---------------------------------------------------------------------------
// K6: redundant pickC (3 × 1024-bin scans) -> exact q1/mu/q3, hinge loss,
//     fused finalize via done counter.  <<<128,256>>>
// ---------------------------------------------------------------------------
__global__ void k_loss(float* __restrict__ out, int E)
{
    __shared__ unsigned sb[NB2 + 1];
    __shared__ unsigned ssc[256];
    __shared__ float    sq[3];
    int t = threadIdx.x;
    for (int k = t; k <= NB2; k += 256) sb[k] = g_boff[k];
    unsigned n = g_n;

    double acc = 0.0;
    if (n) {
        for (int st = 0; st < 3; st++) {
            unsigned rB = g_rB[st];
            unsigned pA = g_pA[st], pB = g_pB[st];
            unsigned loc[4], s = 0;
            #pragma unroll
            for (int k = 0; k < 4; k++) { loc[k] = g_hC[st*1024 + t*4 + k]; s += loc[k]; }
            ssc[t] = s;
            __syncthreads();
            #pragma unroll
            for (int off = 1; off < 256; off <<= 1) {
                unsigned v = ssc[t];
                unsigned a = (t >= off) ? ssc[t - off] : 0u;
                __syncthreads();
                ssc[t] = v + a;
                __syncthreads();
            }
            unsigned inc = ssc[t], exc = inc - s;
            if (s && exc <= rB && rB < inc) {
                unsigned cum = exc;
                #pragma unroll
                for (int k = 0; k < 4; k++) {
                    if (cum + loc[k] > rB) {
                        sq[st] = __uint_as_float((pA << 21) | (pB << 10) | (unsigned)(t*4 + k));
                        break;
                    }
                    cum += loc[k];
                }
            }
            __syncthreads();
        }
        float mu = sq[1];
        float margin = fmaxf(sq[2] - sq[0], 1e-6f) * 0.75f;   // iqr * 0.5 * 1.5
        enumerate<3>(E, sb, 0, 0, mu, margin, acc);
    }

    // block reduce (double) + global accumulate + fused finalize
    for (int o = 16; o; o >>= 1) acc += __shfl_down_sync(0xFFFFFFFFu, acc, o);
    __shared__ double shs[8];
    if ((t & 31) == 0) shs[t >> 5] = acc;
    __syncthreads();
    if (t < 32) {
        double v = (t < 8) ? shs[t] : 0.0;
        for (int o = 4; o; o >>= 1) v += __shfl_down_sync(0xFFFFFFFFu, v, o);
        if (t == 0 && v != 0.0) atomicAdd(&g_sum, v);
    }
    __shared__ bool last;
    if (t == 0) {
        __threadfence();
        last = (atomicAdd(&g_done, 1u) == gridDim.x - 1);
    }
    __syncthreads();
    if (last && t == 0) {
        __threadfence();
        double denom = (double)(n > 0u ? n : 1u);
        out[0] = (float)(*(volatile double*)&g_sum / denom);
    }
}

// ---------------------------------------------------------------------------
extern "C" void kernel_launch(void* const* d_in, const int* in_sizes, int n_in,
                              void* d_out, int out_size)
{
    const float* pos  = (const float*)d_in[0];   // node_positions (B*N, 2)
    // d_in[1] = adjacency: unused
    const int*   eidx = (const int*)d_in[2];     // edge_index (2, E)
    float* out = (float*)d_out;

    int E = in_sizes[2] / 2;
    if (E > EMAX) E = EMAX;

    k_setup<<<32, 256>>>(pos, eidx, E);
    k_fill<<<16, 256>>>(E);
    k_histA<<<128, 256>>>(E);
    k_pickA_histB<<<128, 256>>>(E);
    k_pickB_histC<<<128, 256>>>(E);
    k_loss<<<128, 256>>>(out, E);
}

// round 9
// speedup vs baseline: 4.2115x; 1.3740x over previous
#include <cuda_runtime.h>
#include <math.h>

#define EMAX 4096
#define NB2  256
#define W    8
#define CAPW (EMAX*EMAX)              /* worst-case window-slot buffer */
#define PI_F   3.14159274101257324f
#define THR_F  0.08726646259971647f
#define BSCALE 81.48733086305042f     /* 256/pi */
#define INF_BITS 0x7F800000u

// ---- device scratch (no allocations allowed) ----
__device__ float4   g_i4[EMAX];        // (ang, nx, ny, c) by original edge idx
__device__ float2   g_mid[EMAX];
__device__ int      g_bine[EMAX];
__device__ unsigned g_bcnt[NB2], g_bcur[NB2];
__device__ unsigned g_boff[NB2 + 1];
__device__ unsigned g_bwoff[NB2 + 1]; // window-slot base per bucket
__device__ float4   g_q4[EMAX];        // bucket-order: (ang, mx, my, bitcast(orig idx))
__device__ float    g_bufw[CAPW];      // window slots: dist or +inf
__device__ unsigned g_hA[2048];        // float bits [21..31]
__device__ unsigned g_hB[3 * 2048];    // bits [10..20] per rank
__device__ unsigned g_hC[3 * 1024];    // bits [0..9]  per rank
__device__ unsigned g_n;
__device__ unsigned g_pA[3], g_rA[3];
__device__ unsigned g_pB[3], g_rB[3];
__device__ float    g_q[3];
__device__ unsigned g_done;
__device__ double   g_sum;

// ---------------------------------------------------------------------------
// K1: zero scratch + per-edge geometry + bucket counts.  <<<32,256>>>
// ---------------------------------------------------------------------------
__global__ void k_setup(const float* __restrict__ pos, const int* __restrict__ eidx, int E)
{
    int gtid = blockIdx.x * blockDim.x + threadIdx.x;
    int nt   = gridDim.x * blockDim.x;
    for (int k = gtid; k < 2048;   k += nt) g_hA[k] = 0u;
    for (int k = gtid; k < 3*2048; k += nt) g_hB[k] = 0u;
    for (int k = gtid; k < 3*1024; k += nt) g_hC[k] = 0u;
    if (gtid < NB2) { g_bcnt[gtid] = 0u; g_bcur[gtid] = 0u; }
    if (gtid == 0)  { g_sum = 0.0; g_done = 0u; g_n = 0u; }

    if (gtid < E) {
        int e = gtid;
        int s = eidx[e];
        int d = eidx[E + e];
        float sx = pos[2*s], sy = pos[2*s+1];
        float dx = pos[2*d], dy = pos[2*d+1];
        float vx = dx - sx, vy = dy - sy;
        float len = fmaxf(sqrtf(vx*vx + vy*vy), 1e-8f);
        float ux = vx / len, uy = vy / len;
        float a = atan2f(uy, ux);
        a = fmodf(a, PI_F);
        if (a < 0.f) a += PI_F;
        float nx = -uy, ny = ux;
        g_i4[e]  = make_float4(a, nx, ny, sx*nx + sy*ny);
        g_mid[e] = make_float2((sx + dx) * 0.5f, (sy + dy) * 0.5f);
        int b = (int)(a * BSCALE);
        if (b >= NB2) b = NB2 - 1;
        if (b < 0)    b = 0;
        g_bine[e] = b;
        atomicAdd(&g_bcnt[b], 1u);
    }
}

// ---------------------------------------------------------------------------
// K2: redundant per-block scans (bucket offsets + window-slot bases) +
//     bucket scatter.  <<<16,256>>>
// ---------------------------------------------------------------------------
__global__ void k_fill(int E)
{
    __shared__ unsigned sc[NB2];       // bucket counts
    __shared__ unsigned sbo[NB2];      // bucket offsets (exclusive)
    __shared__ unsigned ssc[NB2];      // scan workspace
    int t = threadIdx.x;

    unsigned c = g_bcnt[t];
    sc[t] = c;
    ssc[t] = c;
    __syncthreads();
    #pragma unroll
    for (int off = 1; off < NB2; off <<= 1) {
        unsigned v = ssc[t];
        unsigned a = (t >= off) ? ssc[t - off] : 0u;
        __syncthreads();
        ssc[t] = v + a;
        __syncthreads();
    }
    unsigned exc = ssc[t] - c;
    sbo[t] = exc;
    g_boff[t] = exc;                                 // identical across blocks
    if (t == NB2 - 1) g_boff[NB2] = ssc[NB2 - 1];
    __syncthreads();

    // window size for bucket t (17 buckets mod 256)
    unsigned Wt = 0;
    #pragma unroll
    for (int d = -W; d <= W; d++) Wt += sc[(t + d + NB2) & (NB2 - 1)];
    unsigned prod = c * Wt;
    ssc[t] = prod;
    __syncthreads();
    #pragma unroll
    for (int off = 1; off < NB2; off <<= 1) {
        unsigned v = ssc[t];
        unsigned a = (t >= off) ? ssc[t - off] : 0u;
        __syncthreads();
        ssc[t] = v + a;
        __syncthreads();
    }
    g_bwoff[t] = ssc[t] - prod;
    if (t == NB2 - 1) g_bwoff[NB2] = ssc[NB2 - 1];   // total T
    __syncthreads();

    int e = blockIdx.x * blockDim.x + t;
    if (e < E) {
        int b = g_bine[e];
        unsigned slot = sbo[b] + atomicAdd(&g_bcur[b], 1u);
        float4 f = g_i4[e];
        float2 m = g_mid[e];
        g_q4[slot] = make_float4(f.x, m.x, m.y, __int_as_float(e));
    }
}

// ---------------------------------------------------------------------------
// K3: SINGLE enumeration — one warp per slot; deterministic output slots
//     (no compaction atomics); shared 2048-bin level-A histogram. <<<256,512>>>
// ---------------------------------------------------------------------------
__global__ void __launch_bounds__(512) k_enum(int E)
{
    __shared__ unsigned sb[NB2 + 1];
    __shared__ unsigned sbw[NB2];
    __shared__ unsigned sh[2048];
    int t = threadIdx.x;
    for (int k = t; k <= NB2; k += 512) sb[k] = g_boff[k];
    for (int k = t; k < NB2;  k += 512) sbw[k] = g_bwoff[k];
    for (int k = t; k < 2048; k += 512) sh[k] = 0u;
    __syncthreads();

    int gw   = (blockIdx.x * blockDim.x + t) >> 5;
    int lane = t & 31;
    int nw   = (gridDim.x * blockDim.x) >> 5;

    for (int s = gw; s < E; s += nw) {
        float4 qs = g_q4[s];
        int u = __float_as_int(qs.w);
        float4 f = g_i4[u];
        float au = f.x, nxu = f.y, nyu = f.z, cu = f.w;
        int b = g_bine[u];
        int lo = b - W, hi = b + W;
        unsigned r0s, r0e, r1s = 0u, r1e = 0u;
        if (lo < 0)         { r0s = sb[lo + NB2]; r0e = sb[NB2]; r1s = sb[0]; r1e = sb[hi + 1]; }
        else if (hi >= NB2) { r0s = sb[lo];       r0e = sb[NB2]; r1s = sb[0]; r1e = sb[hi - NB2 + 1]; }
        else                { r0s = sb[lo];       r0e = sb[hi + 1]; }

        unsigned Wb   = (r0e - r0s) + (r1e - r1s);
        unsigned rank = (unsigned)s - sb[b];
        unsigned base = sbw[b] + rank * Wb;

        unsigned off = 0;
        #pragma unroll
        for (int pass = 0; pass < 2; pass++) {
            unsigned ks = pass ? r1s : r0s;
            unsigned ke = pass ? r1e : r0e;
            for (unsigned k = ks + lane; k < ke; k += 32) {
                float4 q = g_q4[k];
                int v = __float_as_int(q.w);
                float da   = fabsf(au - q.x);
                float circ = fminf(da, PI_F - da);
                float val  = __uint_as_float(INF_BITS);
                if (v > u && circ <= THR_F) {        // exact reference mask
                    val = fabsf(fmaf(nxu, q.y, fmaf(nyu, q.z, -cu)));
                    atomicAdd(&sh[__float_as_uint(val) >> 21], 1u);
                }
                g_bufw[base + off + (k - ks)] = val;
            }
            off += (r0e - r0s);
        }
    }
    __syncthreads();
    for (int k = t; k < 2048; k += 512) {
        unsigned v = sh[k];
        if (v) atomicAdd(&g_hA[k], v);
    }
}

// ---------------------------------------------------------------------------
// K4: redundant pickA + level-B histogram (stream over buffer). <<<128,512>>>
// ---------------------------------------------------------------------------
__global__ void __launch_bounds__(512) k_pickA_histB()
{
    __shared__ unsigned ssc[512];
    __shared__ unsigned sp[3];
    int t = threadIdx.x;
    if (t < 3) sp[t] = 0xFFFFFFFFu;

    unsigned loc[4], s = 0;
    #pragma unroll
    for (int k = 0; k < 4; k++) { loc[k] = g_hA[t*4 + k]; s += loc[k]; }
    ssc[t] = s;
    __syncthreads();
    #pragma unroll
    for (int off = 1; off < 512; off <<= 1) {
        unsigned v = ssc[t];
        unsigned a = (t >= off) ? ssc[t - off] : 0u;
        __syncthreads();
        ssc[t] = v + a;
        __syncthreads();
    }
    unsigned inc = ssc[t], exc = inc - s;
    unsigned n = ssc[511];
    if (t == 0) g_n = n;
    if (!n) return;

    unsigned r[3];
    r[0] = (n/4 > 0u) ? (n/4 - 1u) : 0u;
    r[1] = n/2;
    unsigned q3i = (unsigned)((3ull * n) / 4ull);
    if (q3i > n - 1u) q3i = n - 1u;
    r[2] = q3i;
    #pragma unroll
    for (int st = 0; st < 3; st++) {
        if (s && exc <= r[st] && r[st] < inc) {
            unsigned cum = exc;
            #pragma unroll
            for (int k = 0; k < 4; k++) {
                if (cum + loc[k] > r[st]) {
                    sp[st] = (unsigned)(t*4 + k);
                    g_pA[st] = sp[st];
                    g_rA[st] = r[st] - cum;
                    break;
                }
                cum += loc[k];
            }
        }
    }
    __syncthreads();

    unsigned p0 = sp[0], p1 = sp[1], p2 = sp[2];
    unsigned T = g_bwoff[NB2];
    int stride = gridDim.x * blockDim.x;
    for (unsigned idx = blockIdx.x * blockDim.x + t; idx < T; idx += stride) {
        unsigned bits = __float_as_uint(g_bufw[idx]);   // inf never matches pA
        unsigned a11 = bits >> 21, m11 = (bits >> 10) & 2047u;
        if (a11 == p0) atomicAdd(&g_hB[m11],        1u);
        if (a11 == p1) atomicAdd(&g_hB[2048 + m11], 1u);
        if (a11 == p2) atomicAdd(&g_hB[4096 + m11], 1u);
    }
}

// ---------------------------------------------------------------------------
// K5: redundant pickB + level-C histogram (stream over buffer). <<<128,512>>>
// ---------------------------------------------------------------------------
__global__ void __launch_bounds__(512) k_pickB_histC()
{
    __shared__ unsigned ssc[512];
    __shared__ unsigned spf[3];
    int t = threadIdx.x;
    if (t < 3) spf[t] = 0xFFFFFFFFu;
    unsigned n = g_n;
    if (!n) return;

    for (int st = 0; st < 3; st++) {
        unsigned rA = g_rA[st];
        unsigned pA = g_pA[st];
        unsigned loc[4], s = 0;
        #pragma unroll
        for (int k = 0; k < 4; k++) { loc[k] = g_hB[st*2048 + t*4 + k]; s += loc[k]; }
        ssc[t] = s;
        __syncthreads();
        #pragma unroll
        for (int off = 1; off < 512; off <<= 1) {
            unsigned v = ssc[t];
            unsigned a = (t >= off) ? ssc[t - off] : 0u;
            __syncthreads();
            ssc[t] = v + a;
            __syncthreads();
        }
        unsigned inc = ssc[t], exc = inc - s;
        if (s && exc <= rA && rA < inc) {
            unsigned cum = exc;
            #pragma unroll
            for (int k = 0; k < 4; k++) {
                if (cum + loc[k] > rA) {
                    unsigned pb = (unsigned)(t*4 + k);
                    g_pB[st] = pb;
                    g_rB[st] = rA - cum;
                    spf[st]  = (pA << 11) | pb;
                    break;
                }
                cum += loc[k];
            }
        }
        __syncthreads();
    }

    unsigned p0 = spf[0], p1 = spf[1], p2 = spf[2];
    unsigned T = g_bwoff[NB2];
    int stride = gridDim.x * blockDim.x;
    for (unsigned idx = blockIdx.x * blockDim.x + t; idx < T; idx += stride) {
        unsigned bits = __float_as_uint(g_bufw[idx]);
        unsigned ab22 = bits >> 10, l10 = bits & 1023u;
        if (ab22 == p0) atomicAdd(&g_hC[l10],        1u);
        if (ab22 == p1) atomicAdd(&g_hC[1024 + l10], 1u);
        if (ab22 == p2) atomicAdd(&g_hC[2048 + l10], 1u);
    }
}

// ---------------------------------------------------------------------------
// K6: redundant pickC -> q1/mu/q3, hinge loss over buffer, finalize. <<<128,512>>>
// ---------------------------------------------------------------------------
__global__ void __launch_bounds__(512) k_loss(float* __restrict__ out)
{
    __shared__ unsigned ssc[512];
    __shared__ float    sq[3];
    int t = threadIdx.x;
    if (t < 3) sq[t] = 0.f;
    unsigned n = g_n;

    double acc = 0.0;
    if (n) {
        for (int st = 0; st < 3; st++) {
            unsigned rB = g_rB[st];
            unsigned pA = g_pA[st], pB = g_pB[st];
            unsigned loc[2], s = 0;
            #pragma unroll
            for (int k = 0; k < 2; k++) { loc[k] = g_hC[st*1024 + t*2 + k]; s += loc[k]; }
            ssc[t] = s;
            __syncthreads();
            #pragma unroll
            for (int off = 1; off < 512; off <<= 1) {
                unsigned v = ssc[t];
                unsigned a = (t >= off) ? ssc[t - off] : 0u;
                __syncthreads();
                ssc[t] = v + a;
                __syncthreads();
            }
            unsigned inc = ssc[t], exc = inc - s;
            if (s && exc <= rB && rB < inc) {
                unsigned cum = exc;
                #pragma unroll
                for (int k = 0; k < 2; k++) {
                    if (cum + loc[k] > rB) {
                        sq[st] = __uint_as_float((pA << 21) | (pB << 10) | (unsigned)(t*2 + k));
                        break;
                    }
                    cum += loc[k];
                }
            }
            __syncthreads();
        }
        float mu = sq[1];
        float margin = fmaxf(sq[2] - sq[0], 1e-6f) * 0.75f;   // iqr * 0.5 * 1.5

        unsigned T = g_bwoff[NB2];
        int stride = gridDim.x * blockDim.x;
        for (unsigned idx = blockIdx.x * blockDim.x + t; idx < T; idx += stride) {
            float d = g_bufw[idx];
            if (__float_as_uint(d) < INF_BITS) {     // skip non-qualifying slots
                float h = fabsf(d - mu) - margin;
                if (h > 0.f) acc += (double)h;
            }
        }
    }

    for (int o = 16; o; o >>= 1) acc += __shfl_down_sync(0xFFFFFFFFu, acc, o);
    __shared__ double shs[16];
    if ((t & 31) == 0) shs[t >> 5] = acc;
    __syncthreads();
    if (t < 32) {
        double v = (t < 16) ? shs[t] : 0.0;
        for (int o = 8; o; o >>= 1) v += __shfl_down_sync(0xFFFFFFFFu, v, o);
        if (t == 0 && v != 0.0) atomicAdd(&g_sum, v);
    }
    __shared__ bool last;
    if (t == 0) {
        __threadfence();
        last = (atomicAdd(&g_done, 1u) == gridDim.x - 1);
    }
    __syncthreads();
    if (last && t == 0) {
        __threadfence();
        double denom = (double)(n > 0u ? n : 1u);
        out[0] = (float)(*(volatile double*)&g_sum / denom);
    }
}

// ---------------------------------------------------------------------------
extern "C" void kernel_launch(void* const* d_in, const int* in_sizes, int n_in,
                              void* d_out, int out_size)
{
    const float* pos  = (const float*)d_in[0];   // node_positions (B*N, 2)
    // d_in[1] = adjacency: unused
    const int*   eidx = (const int*)d_in[2];     // edge_index (2, E)
    float* out = (float*)d_out;

    int E = in_sizes[2] / 2;
    if (E > EMAX) E = EMAX;

    k_setup<<<32, 256>>>(pos, eidx, E);
    k_fill<<<16, 256>>>(E);
    k_enum<<<256, 512>>>(E);
    k_pickA_histB<<<128, 512>>>();
    k_pickB_histC<<<128, 512>>>();
    k_loss<<<128, 512>>>(out);
}